// round 3
// baseline (speedup 1.0000x reference)
#include <cuda_runtime.h>
#include <cstdint>

#define BB 4
#define NN 8192
#define FF 64
#define EE 65536
#define KK 4096
#define NW 256   // NN/32
#define KW 128   // KK/32
#define TGT (NN-KK)
#define FULLM 0xffffffffu

// ---------------- device scratch (static; no allocations) ----------------
__device__ unsigned long long g_keys[2][BB][EE];   // 4 MB ping-pong
__device__ unsigned char g_ok[BB][EE];
__device__ unsigned g_sedge[BB][EE];               // packed (a | b<<13 | ok<<26) in sorted order
__device__ float g_vn[BB][NN];
__device__ int g_mask[BB][NN];
__device__ int g_m[BB][NN];
__device__ int g_rank[BB][NN];
__device__ int g_gstart[BB][KK + 1];
__device__ unsigned short g_gsrc[BB][NN];
__device__ unsigned g_At[BB][NN][NW];              // 32 MB : bits of A^T (row j, bit i)
__device__ unsigned g_M1[BB][KK][NW];              // 16 MB : col-merged (as rows of A^T merged)
__device__ unsigned g_M1T[BB][NN][KW];             // 16 MB : transpose of M1
__device__ unsigned g_M2[BB][KK][KW];              // 8 MB  : final K x K bits

// ---------------- utils ----------------
__device__ __forceinline__ unsigned warpScanIncl(unsigned v) {
    int lane = threadIdx.x & 31;
#pragma unroll
    for (int o = 1; o < 32; o <<= 1) {
        unsigned n = __shfl_up_sync(FULLM, v, o);
        if (lane >= o) v += n;
    }
    return v;
}

// block = 1024 threads. s_tmp must have 33 slots. Returns exclusive prefix; *total = block sum.
__device__ __forceinline__ unsigned blockScanExcl1024(unsigned v, unsigned* s_tmp, unsigned* total) {
    int tid = threadIdx.x, lane = tid & 31, wid = tid >> 5;
    __syncthreads();                       // protect s_tmp reuse across calls
    unsigned inc = warpScanIncl(v);
    if (lane == 31) s_tmp[wid] = inc;
    __syncthreads();
    if (wid == 0) {
        unsigned w = s_tmp[lane];
        unsigned wi = warpScanIncl(w);
        s_tmp[lane] = wi - w;
        if (lane == 31) s_tmp[32] = wi;
    }
    __syncthreads();
    *total = s_tmp[32];
    return inc - v + s_tmp[wid];
}

// ---------------- 1. vertex squared norms ----------------
// Emulates XLA GPU row-reduction order:
//   lane partial p_l = x[l]^2 + x[l+32]^2, then butterfly tree 16,8,4,2,1.
__global__ void k_vnorm(const float* __restrict__ image) {
    int idx = blockIdx.x * blockDim.x + threadIdx.x;   // b*NN+v
    if (idx >= BB * NN) return;
    const float* row = image + (size_t)idx * FF;
    float p[32];
#pragma unroll
    for (int l = 0; l < 32; l++) {
        float a = row[l], c = row[l + 32];
        p[l] = __fadd_rn(__fmul_rn(a, a), __fmul_rn(c, c));
    }
#pragma unroll
    for (int off = 16; off >= 1; off >>= 1) {
#pragma unroll
        for (int l = 0; l < 16; l++) {
            if (l < off) p[l] = __fadd_rn(p[l], p[l + off]);
        }
    }
    g_vn[0][idx] = p[0];   // flat view
}

// ---------------- 2. keys + boundary ok ----------------
__global__ void k_keys(const int* __restrict__ edges, const float* __restrict__ vs) {
    int idx = blockIdx.x * blockDim.x + threadIdx.x;
    int b = idx >> 16, e = idx & (EE - 1);
    if (b >= BB) return;
    int a = edges[(size_t)b * 2 * EE + e];
    int v1 = edges[(size_t)b * 2 * EE + EE + e];
    float c = __fadd_rn(g_vn[b][a], g_vn[b][v1]);
    g_keys[0][b][e] = ((unsigned long long)__float_as_uint(c) << 32) | (unsigned)e;
    float ax = vs[((size_t)b * NN + a) * 2 + 0], ay = vs[((size_t)b * NN + a) * 2 + 1];
    float bx = vs[((size_t)b * NN + v1) * 2 + 0], by = vs[((size_t)b * NN + v1) * 2 + 1];
    bool bndA = (ax < 0.05f) | (ax > 0.95f) | (ay < 0.05f) | (ay > 0.95f);
    bool bndB = (bx < 0.05f) | (bx > 0.95f) | (by < 0.05f) | (by > 0.95f);
    g_ok[b][e] = (unsigned char)(!(bndA | bndB));
}

// ---------------- 3. init m = identity ----------------
__global__ void k_initm() {
    int idx = blockIdx.x * blockDim.x + threadIdx.x;
    if (idx < BB * NN) g_m[0][idx] = idx & (NN - 1);
}

// ---------------- 4. radix sort (stable, 8 x 4-bit on high word), 1 block per batch --------
__global__ void __launch_bounds__(1024) k_sort() {
    __shared__ unsigned s_tmp[33];
    int b = blockIdx.x, tid = threadIdx.x;
    int base = tid * (EE / 1024);   // 64 elems / thread, blocked (stable)
#pragma unroll 1
    for (int p = 0; p < 8; p++) {
        unsigned long long* src = g_keys[p & 1][b];
        unsigned long long* dst = g_keys[(p + 1) & 1][b];
        int sh = 32 + p * 4;
        // count (packed 8-bit counters in two u64s)
        unsigned long long c0 = 0, c1 = 0;
#pragma unroll 4
        for (int i = 0; i < 64; i++) {
            unsigned d = (unsigned)(src[base + i] >> sh) & 15u;
            if (d < 8) c0 += 1ull << (8 * d); else c1 += 1ull << (8 * (d - 8));
        }
        unsigned offs[16];
        unsigned tot[16];
#pragma unroll
        for (int d = 0; d < 16; d++) {
            unsigned cd = (unsigned)((d < 8 ? (c0 >> (8 * d)) : (c1 >> (8 * (d - 8)))) & 255u);
            offs[d] = blockScanExcl1024(cd, s_tmp, &tot[d]);
        }
        unsigned run = 0;
#pragma unroll
        for (int d = 0; d < 16; d++) { offs[d] += run; run += tot[d]; }
        // stable scatter
#pragma unroll 4
        for (int i = 0; i < 64; i++) {
            unsigned long long k = src[base + i];
            unsigned d = (unsigned)(k >> sh) & 15u;
            dst[offs[d]++] = k;
        }
        __syncthreads();
    }
}

// ---------------- 5. gather sorted edge info into packed words ----------------
__global__ void k_gather(const int* __restrict__ edges) {
    int idx = blockIdx.x * blockDim.x + threadIdx.x;
    int b = idx >> 16, i = idx & (EE - 1);
    if (b >= BB) return;
    unsigned eid = (unsigned)(g_keys[0][b][i] & 0xffffffffu);
    unsigned a = (unsigned)edges[(size_t)b * 2 * EE + eid];
    unsigned v1 = (unsigned)edges[(size_t)b * 2 * EE + EE + eid];
    unsigned okv = g_ok[b][eid];
    g_sedge[b][i] = a | (v1 << 13) | (okv << 26);
}

// ---------------- 6. greedy collapse (warp-speculative windows) ----------------
__global__ void k_greedy() {
    __shared__ unsigned char s_mask[NN];
    int b = blockIdx.x, lane = threadIdx.x;
    for (int i = lane; i < NN; i += 32) s_mask[i] = 1;
    __syncwarp();
    int nk = 0;
    const int W = EE / 32;
    unsigned cur = g_sedge[b][lane];
    for (int w = 0; w < W; w++) {
        unsigned nxt = (w + 1 < W) ? g_sedge[b][(w + 1) * 32 + lane] : 0u;  // prefetch
        int a = cur & 8191, b2 = (cur >> 13) & 8191, okv = (cur >> 26) & 1;
        int tent = okv && s_mask[a] && s_mask[b2];
        unsigned T = __ballot_sync(FULLM, tent);
        unsigned acc = 0;
        while (T) {
            int t = __ffs(T) - 1; T &= T - 1;
            int at = __shfl_sync(FULLM, a, t);
            int bt = __shfl_sync(FULLM, b2, t);
            unsigned conf = __ballot_sync(FULLM, ((acc >> lane) & 1) && (b2 == at || b2 == bt));
            if (!conf && nk < TGT) { acc |= 1u << t; nk++; }
        }
        if ((acc >> lane) & 1) { s_mask[b2] = 0; g_m[b][b2] = a; }
        __syncwarp();
        if (nk >= TGT) break;
        cur = nxt;
    }
    for (int i = lane; i < NN; i += 32) g_mask[b][i] = s_mask[i];
}

// ---------------- 7. alive ranks + group CSR ----------------
__global__ void __launch_bounds__(1024) k_compact() {
    __shared__ unsigned s_tmp[33];
    __shared__ int s_cnt[KK];
    __shared__ int s_cur[KK];
    int b = blockIdx.x, tid = threadIdx.x;
    // ranks (stable compaction positions)
    int base = tid * 8;
    unsigned mk[8]; unsigned c = 0;
#pragma unroll
    for (int i = 0; i < 8; i++) { mk[i] = (unsigned)g_mask[b][base + i]; c += mk[i]; }
    unsigned tot;
    unsigned ex = blockScanExcl1024(c, s_tmp, &tot);
    int run = (int)ex;
#pragma unroll
    for (int i = 0; i < 8; i++) { g_rank[b][base + i] = run; run += (int)mk[i]; }
    __syncthreads();
    // group counts
    for (int r = tid; r < KK; r += 1024) s_cnt[r] = 0;
    __syncthreads();
    for (int j = tid; j < NN; j += 1024) {
        int t = g_m[b][j];
        if (g_mask[b][t]) { int r = g_rank[b][t]; if (r < KK) atomicAdd(&s_cnt[r], 1); }
    }
    __syncthreads();
    // scan counts -> starts
    int i4 = tid * 4; unsigned cv[4]; unsigned sum = 0;
#pragma unroll
    for (int i = 0; i < 4; i++) { cv[i] = (unsigned)s_cnt[i4 + i]; sum += cv[i]; }
    unsigned tot2;
    unsigned ex2 = blockScanExcl1024(sum, s_tmp, &tot2);
    int run2 = (int)ex2;
#pragma unroll
    for (int i = 0; i < 4; i++) { g_gstart[b][i4 + i] = run2; s_cur[i4 + i] = run2; run2 += (int)cv[i]; }
    if (tid == 1023) g_gstart[b][KK] = run2;
    __syncthreads();
    // fill
    for (int j = tid; j < NN; j += 1024) {
        int t = g_m[b][j];
        if (g_mask[b][t]) {
            int r = g_rank[b][t];
            if (r < KK) { int pos = atomicAdd(&s_cur[r], 1); g_gsrc[b][pos] = (unsigned short)j; }
        }
    }
}

// ---------------- 8. pack A (FLOAT32 0/1) -> bits of A^T (fused pack+transpose) ----------
// tile: 256 rows(i) x 128 cols(j).  grid (NN/128, NN/256, BB)
__device__ __forceinline__ unsigned pk4(float4 q) {
    return (q.x != 0.f ? 1u : 0u) | (q.y != 0.f ? 0x100u : 0u) |
           (q.z != 0.f ? 0x10000u : 0u) | (q.w != 0.f ? 0x1000000u : 0u);
}
__global__ void __launch_bounds__(1024) k_packT(const float* __restrict__ A) {
    __shared__ __align__(16) unsigned char tile[256 * 148];
    __shared__ __align__(16) unsigned outS[1024];
    int b = blockIdx.z, it = blockIdx.y, jt = blockIdx.x;
    int tid = threadIdx.x;
    int c4 = tid & 7, r0 = tid >> 3;
#pragma unroll
    for (int k = 0; k < 2; k++) {
        int r = r0 + k * 128;
        const float4* rp = (const float4*)(A + (((size_t)b * NN + (size_t)it * 256 + r) * NN
                                                + (size_t)jt * 128 + c4 * 16));
        float4 q0 = rp[0], q1 = rp[1], q2 = rp[2], q3 = rp[3];
        unsigned* s = (unsigned*)(tile + r * 148 + c4 * 16);
        s[0] = pk4(q0); s[1] = pk4(q1); s[2] = pk4(q2); s[3] = pk4(q3);
    }
    __syncthreads();
    int w = tid >> 5, lane = tid & 31;
    int iw = w & 7, jb = w >> 3;
    unsigned myword = 0;
#pragma unroll 1
    for (int jj = 0; jj < 32; jj++) {
        unsigned char byte = tile[(iw * 32 + lane) * 148 + jb * 32 + jj];
        unsigned word = __ballot_sync(FULLM, byte != 0);
        if (lane == jj) myword = word;
    }
    outS[(jb * 32 + lane) * 8 + iw] = myword;
    __syncthreads();
    int j = tid >> 3, ww = tid & 7;
    g_At[b][jt * 128 + j][it * 8 + ww] = outS[tid];
}

// ---------------- 9. M1[c] = OR of A^T rows in group(c)  (this IS the column merge) -------
__global__ void __launch_bounds__(1024) k_M1() {
    int b = blockIdx.y;
    int c = blockIdx.x * 4 + (threadIdx.x >> 8);
    int w = threadIdx.x & 255;
    int s = g_gstart[b][c], e = g_gstart[b][c + 1];
    unsigned v = 0;
    for (int i = s; i < e; i++) v |= g_At[b][g_gsrc[b][i]][w];
    g_M1[b][c][w] = v;
}

// ---------------- 10. bit transpose M1 (K x N) -> M1T (N x K) ----------------
// tile: 256 c-rows x 128 j-bits (4 words).  grid (NN/128, KK/256, BB)
__global__ void __launch_bounds__(1024) k_transT() {
    __shared__ __align__(16) unsigned wt[256 * 5];
    __shared__ __align__(16) unsigned outS[1024];
    int b = blockIdx.z, ct = blockIdx.y, jt = blockIdx.x;
    int tid = threadIdx.x;
    {
        int r = tid >> 2, w4 = tid & 3;
        wt[r * 5 + w4] = g_M1[b][ct * 256 + r][jt * 4 + w4];
    }
    __syncthreads();
    int w = tid >> 5, lane = tid & 31;
    int jw = w >> 3, iw = w & 7;
    unsigned s = wt[(iw * 32 + lane) * 5 + jw];
    unsigned myword = 0;
#pragma unroll 1
    for (int k = 0; k < 32; k++) {
        unsigned bt = __ballot_sync(FULLM, (s >> k) & 1);
        if (lane == k) myword = bt;
    }
    outS[(jw * 32 + lane) * 8 + iw] = myword;
    __syncthreads();
    int j = tid >> 3, ww = tid & 7;
    g_M1T[b][jt * 128 + j][ct * 8 + ww] = outS[tid];
}

// ---------------- 11. M2[r] = OR of M1T rows in group(r)  (row merge) ----------------
__global__ void __launch_bounds__(1024) k_M2() {
    int b = blockIdx.y;
    int r = blockIdx.x * 8 + (threadIdx.x >> 7);
    int w = threadIdx.x & 127;
    int s = g_gstart[b][r], e = g_gstart[b][r + 1];
    unsigned v = 0;
    for (int i = s; i < e; i++) v |= g_M1T[b][g_gsrc[b][i]][w];
    g_M2[b][r][w] = v;
}

// ---------------- 12. expand bits -> float, clear diagonal ----------------
__global__ void k_expand(float* __restrict__ out) {
    int b = blockIdx.y;
    int idx = blockIdx.x * blockDim.x + threadIdx.x;     // 0 .. K*K/4-1
    int r = idx >> 10;
    int c4 = (idx & 1023) << 2;
    unsigned wv = g_M2[b][r][c4 >> 5];
    int sh = c4 & 31;
    float4 o;
    o.x = (((wv >> (sh + 0)) & 1) && (r != c4 + 0)) ? 1.f : 0.f;
    o.y = (((wv >> (sh + 1)) & 1) && (r != c4 + 1)) ? 1.f : 0.f;
    o.z = (((wv >> (sh + 2)) & 1) && (r != c4 + 2)) ? 1.f : 0.f;
    o.w = (((wv >> (sh + 3)) & 1) && (r != c4 + 3)) ? 1.f : 0.f;
    ((float4*)out)[((size_t)b * KK + r) * (KK / 4) + (idx & 1023)] = o;
}

// ---------------- 13. pooled features ----------------
__global__ void k_feat(const float* __restrict__ image, float* __restrict__ out) {
    int idx = blockIdx.x * blockDim.x + threadIdx.x;   // b*K*F + r*F + f
    int f = idx & (FF - 1);
    int r = (idx >> 6) & (KK - 1);
    int b = idx >> 18;
    if (b >= BB) return;
    int s = g_gstart[b][r], e = g_gstart[b][r + 1];
    float acc = 0.f;
    for (int i = s; i < e; i++) {
        int j = g_gsrc[b][i];
        acc += image[((size_t)b * NN + j) * FF + f];
    }
    out[(size_t)BB * KK * KK + ((size_t)b * KK + r) * FF + f] = acc;
}

// ---------------- launch ----------------
extern "C" void kernel_launch(void* const* d_in, const int* in_sizes, int n_in,
                              void* d_out, int out_size) {
    const float* adj = (const float*)d_in[0];       // bool promoted to f32 (0.0/1.0)
    const float* image = (const float*)d_in[1];
    const float* vs = (const float*)d_in[2];
    const int* edges = (const int*)d_in[3];
    float* out = (float*)d_out;

    k_packT<<<dim3(NN / 128, NN / 256, BB), 1024>>>(adj);
    k_vnorm<<<(BB * NN) / 256, 256>>>(image);
    k_keys<<<(BB * EE) / 256, 256>>>(edges, vs);
    k_initm<<<(BB * NN) / 256, 256>>>();
    k_sort<<<BB, 1024>>>();
    k_gather<<<(BB * EE) / 256, 256>>>(edges);
    k_greedy<<<BB, 32>>>();
    k_compact<<<BB, 1024>>>();
    k_M1<<<dim3(KK / 4, BB), 1024>>>();
    k_transT<<<dim3(NN / 128, KK / 256, BB), 1024>>>();
    k_M2<<<dim3(KK / 8, BB), 1024>>>();
    k_expand<<<dim3((KK * KK / 4) / 256, BB), 256>>>(out);
    k_feat<<<(BB * KK * FF) / 256, 256>>>(image, out);
}

// round 4
// speedup vs baseline: 1.6641x; 1.6641x over previous
#include <cuda_runtime.h>
#include <cstdint>

#define BB 4
#define NN 8192
#define FF 64
#define EE 65536
#define KK 4096
#define NW 256   // NN/32
#define KW 128   // KK/32
#define TGT (NN-KK)
#define FULLM 0xffffffffu
#define NBLK 128   // radix sort blocks per batch (512 keys each)

// ---------------- device scratch (static; no allocations) ----------------
__device__ unsigned long long g_keys[2][BB][EE];   // 4 MB ping-pong
__device__ unsigned char g_ok[BB][EE];
__device__ unsigned g_sedge[BB][EE];               // packed (a | b<<13 | ok<<26) sorted
__device__ float g_vn[BB][NN];
__device__ int g_mask[BB][NN];
__device__ int g_m[BB][NN];
__device__ int g_rank[BB][NN];
__device__ int g_gstart[BB][KK + 1];
__device__ unsigned short g_gsrc[BB][NN];
__device__ unsigned g_hist[BB][256 * NBLK];        // radix histograms
__device__ unsigned g_histS[BB][256 * NBLK];       // scanned
__device__ unsigned g_At[BB][NN][NW];              // 32 MB : bits of A^T (row j, bit i)
__device__ unsigned g_M1[BB][KK][NW];              // 16 MB : col-merged
__device__ unsigned g_M1T[BB][NN][KW];             // 16 MB : transpose of M1
__device__ unsigned g_M2[BB][KK][KW];              // 8 MB  : final K x K bits

// ---------------- utils ----------------
__device__ __forceinline__ unsigned warpScanIncl(unsigned v) {
    int lane = threadIdx.x & 31;
#pragma unroll
    for (int o = 1; o < 32; o <<= 1) {
        unsigned n = __shfl_up_sync(FULLM, v, o);
        if (lane >= o) v += n;
    }
    return v;
}

__device__ __forceinline__ unsigned blockScanExcl1024(unsigned v, unsigned* s_tmp, unsigned* total) {
    int tid = threadIdx.x, lane = tid & 31, wid = tid >> 5;
    __syncthreads();
    unsigned inc = warpScanIncl(v);
    if (lane == 31) s_tmp[wid] = inc;
    __syncthreads();
    if (wid == 0) {
        unsigned w = s_tmp[lane];
        unsigned wi = warpScanIncl(w);
        s_tmp[lane] = wi - w;
        if (lane == 31) s_tmp[32] = wi;
    }
    __syncthreads();
    *total = s_tmp[32];
    return inc - v + s_tmp[wid];
}

// ---------------- 1. vertex squared norms (XLA-order reduction) ----------------
__global__ void k_vnorm(const float* __restrict__ image) {
    int idx = blockIdx.x * blockDim.x + threadIdx.x;
    if (idx >= BB * NN) return;
    const float* row = image + (size_t)idx * FF;
    float p[32];
#pragma unroll
    for (int l = 0; l < 32; l++) {
        float a = row[l], c = row[l + 32];
        p[l] = __fadd_rn(__fmul_rn(a, a), __fmul_rn(c, c));
    }
#pragma unroll
    for (int off = 16; off >= 1; off >>= 1) {
#pragma unroll
        for (int l = 0; l < 16; l++) {
            if (l < off) p[l] = __fadd_rn(p[l], p[l + off]);
        }
    }
    g_vn[0][idx] = p[0];
}

// ---------------- 2. keys + boundary ok ----------------
__global__ void k_keys(const int* __restrict__ edges, const float* __restrict__ vs) {
    int idx = blockIdx.x * blockDim.x + threadIdx.x;
    int b = idx >> 16, e = idx & (EE - 1);
    if (b >= BB) return;
    int a = edges[(size_t)b * 2 * EE + e];
    int v1 = edges[(size_t)b * 2 * EE + EE + e];
    float c = __fadd_rn(g_vn[b][a], g_vn[b][v1]);
    g_keys[0][b][e] = ((unsigned long long)__float_as_uint(c) << 32) | (unsigned)e;
    float ax = vs[((size_t)b * NN + a) * 2 + 0], ay = vs[((size_t)b * NN + a) * 2 + 1];
    float bx = vs[((size_t)b * NN + v1) * 2 + 0], by = vs[((size_t)b * NN + v1) * 2 + 1];
    bool bndA = (ax < 0.05f) | (ax > 0.95f) | (ay < 0.05f) | (ay > 0.95f);
    bool bndB = (bx < 0.05f) | (bx > 0.95f) | (by < 0.05f) | (by > 0.95f);
    g_ok[b][e] = (unsigned char)(!(bndA | bndB));
}

// ---------------- 3. init m = identity ----------------
__global__ void k_initm() {
    int idx = blockIdx.x * blockDim.x + threadIdx.x;
    if (idx < BB * NN) g_m[0][idx] = idx & (NN - 1);
}

// ---------------- 4. multi-block stable LSD radix sort: 4 passes x 8-bit ----------------
__global__ void k_count(int p) {
    __shared__ unsigned s_h[256];
    int b = blockIdx.y, blk = blockIdx.x, t = threadIdx.x;
    s_h[t] = 0;
    __syncthreads();
    const unsigned long long* src = g_keys[p & 1][b];
    int sh = 32 + 8 * p;
    unsigned long long k0 = src[blk * 512 + t], k1 = src[blk * 512 + 256 + t];
    atomicAdd(&s_h[(unsigned)(k0 >> sh) & 255u], 1u);
    atomicAdd(&s_h[(unsigned)(k1 >> sh) & 255u], 1u);
    __syncthreads();
    g_hist[b][t * NBLK + blk] = s_h[t];
}

__global__ void __launch_bounds__(1024) k_scan() {
    __shared__ unsigned s_tmp[33];
    int b = blockIdx.x, t = threadIdx.x;
    unsigned v[32]; unsigned sum = 0;
    int base = t * 32;
#pragma unroll
    for (int i = 0; i < 32; i++) { v[i] = g_hist[b][base + i]; sum += v[i]; }
    unsigned tot;
    unsigned ex = blockScanExcl1024(sum, s_tmp, &tot);
    unsigned run = ex;
#pragma unroll
    for (int i = 0; i < 32; i++) { g_histS[b][base + i] = run; run += v[i]; }
}

__global__ void __launch_bounds__(256) k_scat(int p) {
    __shared__ unsigned s_wcnt[8 * 256];
    __shared__ unsigned s_pre[8 * 256];
    __shared__ unsigned s_base[256];
    int b = blockIdx.y, blk = blockIdx.x, t = threadIdx.x, lane = t & 31, w = t >> 5;
    const unsigned long long* src = g_keys[p & 1][b];
    unsigned long long* dst = g_keys[(p + 1) & 1][b];
    int sh = 32 + 8 * p;
#pragma unroll
    for (int k = 0; k < 8; k++) s_wcnt[k * 256 + t] = 0;
    s_base[t] = g_histS[b][t * NBLK + blk];
    unsigned long long kk[2] = { src[blk * 512 + t], src[blk * 512 + 256 + t] };
    __syncthreads();
#pragma unroll
    for (int i = 0; i < 2; i++) {
        unsigned d = (unsigned)(kk[i] >> sh) & 255u;
        unsigned m = FULLM;
#pragma unroll
        for (int bit = 0; bit < 8; bit++) {
            unsigned bl = __ballot_sync(FULLM, (d >> bit) & 1u);
            m &= ((d >> bit) & 1u) ? bl : ~bl;
        }
        unsigned below = (1u << lane) - 1u;
        unsigned rw = __popc(m & below);
        if (rw == 0) s_wcnt[w * 256 + d] = __popc(m);
        __syncthreads();
        unsigned run = s_base[t];
#pragma unroll
        for (int w2 = 0; w2 < 8; w2++) { s_pre[w2 * 256 + t] = run; run += s_wcnt[w2 * 256 + t]; }
        s_base[t] = run;
        __syncthreads();
        dst[s_pre[w * 256 + d] + rw] = kk[i];
        if (rw == 0) s_wcnt[w * 256 + d] = 0;
        __syncthreads();
    }
}

// ---------------- 5. gather sorted edge info into packed words ----------------
__global__ void k_gather(const int* __restrict__ edges) {
    int idx = blockIdx.x * blockDim.x + threadIdx.x;
    int b = idx >> 16, i = idx & (EE - 1);
    if (b >= BB) return;
    unsigned eid = (unsigned)(g_keys[0][b][i] & 0xffffffffu);
    unsigned a = (unsigned)edges[(size_t)b * 2 * EE + eid];
    unsigned v1 = (unsigned)edges[(size_t)b * 2 * EE + EE + eid];
    unsigned okv = g_ok[b][eid];
    g_sedge[b][i] = a | (v1 << 13) | (okv << 26);
}

// ---------------- 6. greedy collapse: O(1) window probe + serial fallback ----------------
__global__ void k_greedy() {
    __shared__ unsigned char s_mask[NN];
    __shared__ unsigned short s_tag[NN];   // epoch-tagged a-value marks (no init needed)
    __shared__ unsigned short s_own[NN];   // b-value ownership (w*32+lane unique, no init)
    int b = blockIdx.x, lane = threadIdx.x;
    for (int i = lane; i < NN; i += 32) s_mask[i] = 1;
    __syncwarp();
    int nk = 0;
    const int W = EE / 32;
    unsigned cur = g_sedge[b][lane];
    for (int w = 0; w < W; w++) {
        unsigned nxt = (w + 1 < W) ? g_sedge[b][(w + 1) * 32 + lane] : 0u;
        int a = cur & 8191, b2 = (cur >> 13) & 8191, okv = (cur >> 26) & 1;
        int tent = okv && s_mask[a] && s_mask[b2];
        unsigned T = __ballot_sync(FULLM, tent);
        if (T) {
            // conservative conflict probe: any b equal to any a, or duplicate b's
            if (tent) s_tag[a] = (unsigned short)w;
            __syncwarp();
            if (tent) s_own[b2] = (unsigned short)(w * 32 + lane);
            __syncwarp();
            int bad = 0;
            if (tent) {
                bad = (s_tag[b2] == (unsigned short)w) ||
                      (s_own[b2] != (unsigned short)(w * 32 + lane));
            }
            unsigned D = __ballot_sync(FULLM, bad);
            unsigned below = (1u << lane) - 1u;
            unsigned acc = 0;
            int cnt = __popc(T);
            if (!D) {
                if (nk + cnt <= TGT) { acc = T; nk += cnt; }
                else {
                    int rem = TGT - nk;
                    acc = __ballot_sync(FULLM, tent && (__popc(T & below) < rem));
                    nk = TGT;
                }
            } else {
                // serial fallback (exact sequential semantics)
                unsigned TT = T;
                while (TT) {
                    int t2 = __ffs(TT) - 1; TT &= TT - 1;
                    int at = __shfl_sync(FULLM, a, t2);
                    int bt = __shfl_sync(FULLM, b2, t2);
                    unsigned conf = __ballot_sync(FULLM, ((acc >> lane) & 1) && (b2 == at || b2 == bt));
                    if (!conf && nk < TGT) { acc |= 1u << t2; nk++; }
                }
            }
            if ((acc >> lane) & 1) { s_mask[b2] = 0; g_m[b][b2] = a; }
            __syncwarp();
            if (nk >= TGT) break;
        }
        cur = nxt;
    }
    for (int i = lane; i < NN; i += 32) g_mask[b][i] = s_mask[i];
}

// ---------------- 7. alive ranks + group CSR ----------------
__global__ void __launch_bounds__(1024) k_compact() {
    __shared__ unsigned s_tmp[33];
    __shared__ int s_cnt[KK];
    __shared__ int s_cur[KK];
    int b = blockIdx.x, tid = threadIdx.x;
    int base = tid * 8;
    unsigned mk[8]; unsigned c = 0;
#pragma unroll
    for (int i = 0; i < 8; i++) { mk[i] = (unsigned)g_mask[b][base + i]; c += mk[i]; }
    unsigned tot;
    unsigned ex = blockScanExcl1024(c, s_tmp, &tot);
    int run = (int)ex;
#pragma unroll
    for (int i = 0; i < 8; i++) { g_rank[b][base + i] = run; run += (int)mk[i]; }
    __syncthreads();
    for (int r = tid; r < KK; r += 1024) s_cnt[r] = 0;
    __syncthreads();
    for (int j = tid; j < NN; j += 1024) {
        int t = g_m[b][j];
        if (g_mask[b][t]) { int r = g_rank[b][t]; if (r < KK) atomicAdd(&s_cnt[r], 1); }
    }
    __syncthreads();
    int i4 = tid * 4; unsigned cv[4]; unsigned sum = 0;
#pragma unroll
    for (int i = 0; i < 4; i++) { cv[i] = (unsigned)s_cnt[i4 + i]; sum += cv[i]; }
    unsigned tot2;
    unsigned ex2 = blockScanExcl1024(sum, s_tmp, &tot2);
    int run2 = (int)ex2;
#pragma unroll
    for (int i = 0; i < 4; i++) { g_gstart[b][i4 + i] = run2; s_cur[i4 + i] = run2; run2 += (int)cv[i]; }
    if (tid == 1023) g_gstart[b][KK] = run2;
    __syncthreads();
    for (int j = tid; j < NN; j += 1024) {
        int t = g_m[b][j];
        if (g_mask[b][t]) {
            int r = g_rank[b][t];
            if (r < KK) { int pos = atomicAdd(&s_cur[r], 1); g_gsrc[b][pos] = (unsigned short)j; }
        }
    }
}

// ---------------- 8. pack A (f32 0/1) -> bits of A^T ----------------
__device__ __forceinline__ unsigned pk4(float4 q) {
    return (q.x != 0.f ? 1u : 0u) | (q.y != 0.f ? 0x100u : 0u) |
           (q.z != 0.f ? 0x10000u : 0u) | (q.w != 0.f ? 0x1000000u : 0u);
}
__global__ void __launch_bounds__(1024) k_packT(const float* __restrict__ A) {
    __shared__ __align__(16) unsigned char tile[256 * 148];
    __shared__ __align__(16) unsigned outS[1024];
    int b = blockIdx.z, it = blockIdx.y, jt = blockIdx.x;
    int tid = threadIdx.x;
    int c4 = tid & 7, r0 = tid >> 3;
#pragma unroll
    for (int k = 0; k < 2; k++) {
        int r = r0 + k * 128;
        const float4* rp = (const float4*)(A + (((size_t)b * NN + (size_t)it * 256 + r) * NN
                                                + (size_t)jt * 128 + c4 * 16));
        float4 q0 = rp[0], q1 = rp[1], q2 = rp[2], q3 = rp[3];
        unsigned* s = (unsigned*)(tile + r * 148 + c4 * 16);
        s[0] = pk4(q0); s[1] = pk4(q1); s[2] = pk4(q2); s[3] = pk4(q3);
    }
    __syncthreads();
    int w = tid >> 5, lane = tid & 31;
    int iw = w & 7, jb = w >> 3;
    unsigned myword = 0;
#pragma unroll 1
    for (int jj = 0; jj < 32; jj++) {
        unsigned char byte = tile[(iw * 32 + lane) * 148 + jb * 32 + jj];
        unsigned word = __ballot_sync(FULLM, byte != 0);
        if (lane == jj) myword = word;
    }
    outS[(jb * 32 + lane) * 8 + iw] = myword;
    __syncthreads();
    int j = tid >> 3, ww = tid & 7;
    g_At[b][jt * 128 + j][it * 8 + ww] = outS[tid];
}

// ---------------- 9. M1[c] = OR of A^T rows in group(c) ----------------
__global__ void __launch_bounds__(1024) k_M1() {
    int b = blockIdx.y;
    int c = blockIdx.x * 4 + (threadIdx.x >> 8);
    int w = threadIdx.x & 255;
    int s = g_gstart[b][c], e = g_gstart[b][c + 1];
    unsigned v = 0;
    for (int i = s; i < e; i++) v |= g_At[b][g_gsrc[b][i]][w];
    g_M1[b][c][w] = v;
}

// ---------------- 10. bit transpose M1 (K x N) -> M1T (N x K) ----------------
__global__ void __launch_bounds__(1024) k_transT() {
    __shared__ __align__(16) unsigned wt[256 * 5];
    __shared__ __align__(16) unsigned outS[1024];
    int b = blockIdx.z, ct = blockIdx.y, jt = blockIdx.x;
    int tid = threadIdx.x;
    {
        int r = tid >> 2, w4 = tid & 3;
        wt[r * 5 + w4] = g_M1[b][ct * 256 + r][jt * 4 + w4];
    }
    __syncthreads();
    int w = tid >> 5, lane = tid & 31;
    int jw = w >> 3, iw = w & 7;
    unsigned s = wt[(iw * 32 + lane) * 5 + jw];
    unsigned myword = 0;
#pragma unroll 1
    for (int k = 0; k < 32; k++) {
        unsigned bt = __ballot_sync(FULLM, (s >> k) & 1);
        if (lane == k) myword = bt;
    }
    outS[(jw * 32 + lane) * 8 + iw] = myword;
    __syncthreads();
    int j = tid >> 3, ww = tid & 7;
    g_M1T[b][jt * 128 + j][ct * 8 + ww] = outS[tid];
}

// ---------------- 11. M2[r] = OR of M1T rows in group(r) ----------------
__global__ void __launch_bounds__(1024) k_M2() {
    int b = blockIdx.y;
    int r = blockIdx.x * 8 + (threadIdx.x >> 7);
    int w = threadIdx.x & 127;
    int s = g_gstart[b][r], e = g_gstart[b][r + 1];
    unsigned v = 0;
    for (int i = s; i < e; i++) v |= g_M1T[b][g_gsrc[b][i]][w];
    g_M2[b][r][w] = v;
}

// ---------------- 12. expand bits -> float, clear diagonal ----------------
__global__ void k_expand(float* __restrict__ out) {
    int b = blockIdx.y;
    int idx = blockIdx.x * blockDim.x + threadIdx.x;
    int r = idx >> 10;
    int c4 = (idx & 1023) << 2;
    unsigned wv = g_M2[b][r][c4 >> 5];
    int sh = c4 & 31;
    float4 o;
    o.x = (((wv >> (sh + 0)) & 1) && (r != c4 + 0)) ? 1.f : 0.f;
    o.y = (((wv >> (sh + 1)) & 1) && (r != c4 + 1)) ? 1.f : 0.f;
    o.z = (((wv >> (sh + 2)) & 1) && (r != c4 + 2)) ? 1.f : 0.f;
    o.w = (((wv >> (sh + 3)) & 1) && (r != c4 + 3)) ? 1.f : 0.f;
    ((float4*)out)[((size_t)b * KK + r) * (KK / 4) + (idx & 1023)] = o;
}

// ---------------- 13. pooled features ----------------
__global__ void k_feat(const float* __restrict__ image, float* __restrict__ out) {
    int idx = blockIdx.x * blockDim.x + threadIdx.x;
    int f = idx & (FF - 1);
    int r = (idx >> 6) & (KK - 1);
    int b = idx >> 18;
    if (b >= BB) return;
    int s = g_gstart[b][r], e = g_gstart[b][r + 1];
    float acc = 0.f;
    for (int i = s; i < e; i++) {
        int j = g_gsrc[b][i];
        acc += image[((size_t)b * NN + j) * FF + f];
    }
    out[(size_t)BB * KK * KK + ((size_t)b * KK + r) * FF + f] = acc;
}

// ---------------- launch ----------------
extern "C" void kernel_launch(void* const* d_in, const int* in_sizes, int n_in,
                              void* d_out, int out_size) {
    const float* adj = (const float*)d_in[0];       // bool promoted to f32 (0.0/1.0)
    const float* image = (const float*)d_in[1];
    const float* vs = (const float*)d_in[2];
    const int* edges = (const int*)d_in[3];
    float* out = (float*)d_out;

    static cudaStream_t s1 = nullptr;
    static cudaEvent_t evF = nullptr, evJ = nullptr;
    if (!s1) {
        cudaStreamCreateWithFlags(&s1, cudaStreamNonBlocking);
        cudaEventCreateWithFlags(&evF, cudaEventDisableTiming);
        cudaEventCreateWithFlags(&evJ, cudaEventDisableTiming);
    }

    // fork: packT (1GB adj read) overlaps the whole cost/sort/greedy chain
    cudaEventRecord(evF, 0);
    cudaStreamWaitEvent(s1, evF, 0);
    k_packT<<<dim3(NN / 128, NN / 256, BB), 1024, 0, s1>>>(adj);

    k_vnorm<<<(BB * NN) / 256, 256>>>(image);
    k_keys<<<(BB * EE) / 256, 256>>>(edges, vs);
    k_initm<<<(BB * NN) / 256, 256>>>();
    for (int p = 0; p < 4; p++) {
        k_count<<<dim3(NBLK, BB), 256>>>(p);
        k_scan<<<BB, 1024>>>();
        k_scat<<<dim3(NBLK, BB), 256>>>(p);
    }
    k_gather<<<(BB * EE) / 256, 256>>>(edges);
    k_greedy<<<BB, 32>>>();
    k_compact<<<BB, 1024>>>();

    // join packT before merges
    cudaEventRecord(evJ, s1);
    cudaStreamWaitEvent(0, evJ, 0);

    k_M1<<<dim3(KK / 4, BB), 1024>>>();
    k_transT<<<dim3(NN / 128, KK / 256, BB), 1024>>>();
    k_M2<<<dim3(KK / 8, BB), 1024>>>();
    k_expand<<<dim3((KK * KK / 4) / 256, BB), 256>>>(out);
    k_feat<<<(BB * KK * FF) / 256, 256>>>(image, out);
}

// round 5
// speedup vs baseline: 1.7727x; 1.0652x over previous
#include <cuda_runtime.h>
#include <cstdint>

#define BB 4
#define NN 8192
#define FF 64
#define EE 65536
#define KK 4096
#define NW 256   // NN/32
#define KW 128   // KK/32
#define TGT (NN-KK)
#define FULLM 0xffffffffu
#define NBLK 128   // radix sort blocks per batch (512 keys each)

// ---------------- device scratch (static; no allocations) ----------------
__device__ unsigned long long g_keys[2][BB][EE];   // ping-pong
__device__ unsigned char g_ok[BB][EE];
__device__ unsigned g_sedge[BB][EE];               // packed (a | b<<13 | ok<<26) sorted
__device__ float g_vn[BB][NN];
__device__ int g_mask[BB][NN];
__device__ int g_m[BB][NN];
__device__ int g_rank[BB][NN];
__device__ int g_gstart[BB][KK + 1];
__device__ unsigned short g_gsrc[BB][NN];
__device__ unsigned g_hist[BB][256 * NBLK];
__device__ unsigned g_histS[BB][256 * NBLK];
__device__ unsigned g_Ab[BB][NN][NW];              // 32 MB : row-major bits of A
__device__ unsigned g_G1[BB][KK][NW];              // 16 MB : row-merged (A1 on alive rows)
__device__ unsigned g_G1T[BB][NN][KW];             // 16 MB : transpose of G1
__device__ unsigned g_G2[BB][KK][KW];              // 8 MB  : col-merged (transposed final)
__device__ unsigned g_M2[BB][KK][KW];              // 8 MB  : final K x K bits (row-major)

// ---------------- utils ----------------
__device__ __forceinline__ unsigned warpScanIncl(unsigned v) {
    int lane = threadIdx.x & 31;
#pragma unroll
    for (int o = 1; o < 32; o <<= 1) {
        unsigned n = __shfl_up_sync(FULLM, v, o);
        if (lane >= o) v += n;
    }
    return v;
}

__device__ __forceinline__ unsigned blockScanExcl1024(unsigned v, unsigned* s_tmp, unsigned* total) {
    int tid = threadIdx.x, lane = tid & 31, wid = tid >> 5;
    __syncthreads();
    unsigned inc = warpScanIncl(v);
    if (lane == 31) s_tmp[wid] = inc;
    __syncthreads();
    if (wid == 0) {
        unsigned w = s_tmp[lane];
        unsigned wi = warpScanIncl(w);
        s_tmp[lane] = wi - w;
        if (lane == 31) s_tmp[32] = wi;
    }
    __syncthreads();
    *total = s_tmp[32];
    return inc - v + s_tmp[wid];
}

// ---------------- 1. vertex squared norms (XLA-order) + init m ----------------
__global__ void k_vnorm(const float* __restrict__ image) {
    int idx = blockIdx.x * blockDim.x + threadIdx.x;
    if (idx >= BB * NN) return;
    const float* row = image + (size_t)idx * FF;
    float p[32];
#pragma unroll
    for (int l = 0; l < 32; l++) {
        float a = row[l], c = row[l + 32];
        p[l] = __fadd_rn(__fmul_rn(a, a), __fmul_rn(c, c));
    }
#pragma unroll
    for (int off = 16; off >= 1; off >>= 1) {
#pragma unroll
        for (int l = 0; l < 16; l++) {
            if (l < off) p[l] = __fadd_rn(p[l], p[l + off]);
        }
    }
    g_vn[0][idx] = p[0];
    g_m[0][idx] = idx & (NN - 1);     // fused identity init
}

// ---------------- 2. keys + boundary ok ----------------
__global__ void k_keys(const int* __restrict__ edges, const float* __restrict__ vs) {
    int idx = blockIdx.x * blockDim.x + threadIdx.x;
    int b = idx >> 16, e = idx & (EE - 1);
    if (b >= BB) return;
    int a = edges[(size_t)b * 2 * EE + e];
    int v1 = edges[(size_t)b * 2 * EE + EE + e];
    float c = __fadd_rn(g_vn[b][a], g_vn[b][v1]);
    g_keys[0][b][e] = ((unsigned long long)__float_as_uint(c) << 32) | (unsigned)e;
    float ax = vs[((size_t)b * NN + a) * 2 + 0], ay = vs[((size_t)b * NN + a) * 2 + 1];
    float bx = vs[((size_t)b * NN + v1) * 2 + 0], by = vs[((size_t)b * NN + v1) * 2 + 1];
    bool bndA = (ax < 0.05f) | (ax > 0.95f) | (ay < 0.05f) | (ay > 0.95f);
    bool bndB = (bx < 0.05f) | (bx > 0.95f) | (by < 0.05f) | (by > 0.95f);
    g_ok[b][e] = (unsigned char)(!(bndA | bndB));
}

// ---------------- 4. multi-block stable LSD radix sort: 4 passes x 8-bit ----------------
__global__ void k_count(int p) {
    __shared__ unsigned s_h[256];
    int b = blockIdx.y, blk = blockIdx.x, t = threadIdx.x;
    s_h[t] = 0;
    __syncthreads();
    const unsigned long long* src = g_keys[p & 1][b];
    int sh = 32 + 8 * p;
    unsigned long long k0 = src[blk * 512 + t], k1 = src[blk * 512 + 256 + t];
    atomicAdd(&s_h[(unsigned)(k0 >> sh) & 255u], 1u);
    atomicAdd(&s_h[(unsigned)(k1 >> sh) & 255u], 1u);
    __syncthreads();
    g_hist[b][t * NBLK + blk] = s_h[t];
}

__global__ void __launch_bounds__(1024) k_scan() {
    __shared__ unsigned s_tmp[33];
    int b = blockIdx.x, t = threadIdx.x;
    unsigned v[32]; unsigned sum = 0;
    int base = t * 32;
#pragma unroll
    for (int i = 0; i < 32; i++) { v[i] = g_hist[b][base + i]; sum += v[i]; }
    unsigned tot;
    unsigned ex = blockScanExcl1024(sum, s_tmp, &tot);
    unsigned run = ex;
#pragma unroll
    for (int i = 0; i < 32; i++) { g_histS[b][base + i] = run; run += v[i]; }
}

// last pass writes g_sedge directly (fused gather)
__global__ void __launch_bounds__(256) k_scat(int p, const int* __restrict__ edges, int last) {
    __shared__ unsigned s_wcnt[8 * 256];
    __shared__ unsigned s_pre[8 * 256];
    __shared__ unsigned s_base[256];
    int b = blockIdx.y, blk = blockIdx.x, t = threadIdx.x, lane = t & 31, w = t >> 5;
    const unsigned long long* src = g_keys[p & 1][b];
    unsigned long long* dst = g_keys[(p + 1) & 1][b];
    int sh = 32 + 8 * p;
#pragma unroll
    for (int k = 0; k < 8; k++) s_wcnt[k * 256 + t] = 0;
    s_base[t] = g_histS[b][t * NBLK + blk];
    unsigned long long kk[2] = { src[blk * 512 + t], src[blk * 512 + 256 + t] };
    __syncthreads();
#pragma unroll
    for (int i = 0; i < 2; i++) {
        unsigned d = (unsigned)(kk[i] >> sh) & 255u;
        unsigned m = __match_any_sync(FULLM, d);
        unsigned below = (1u << lane) - 1u;
        unsigned rw = __popc(m & below);
        if (rw == 0) s_wcnt[w * 256 + d] = __popc(m);
        __syncthreads();
        unsigned run = s_base[t];
#pragma unroll
        for (int w2 = 0; w2 < 8; w2++) { s_pre[w2 * 256 + t] = run; run += s_wcnt[w2 * 256 + t]; }
        s_base[t] = run;
        __syncthreads();
        unsigned pos = s_pre[w * 256 + d] + rw;
        if (!last) {
            dst[pos] = kk[i];
        } else {
            unsigned eid = (unsigned)(kk[i] & 0xffffffffu);
            unsigned a = (unsigned)edges[(size_t)b * 2 * EE + eid];
            unsigned v1 = (unsigned)edges[(size_t)b * 2 * EE + EE + eid];
            unsigned okv = g_ok[b][eid];
            g_sedge[b][pos] = a | (v1 << 13) | (okv << 26);
        }
        if (rw == 0) s_wcnt[w * 256 + d] = 0;
        __syncthreads();
    }
}

// ---------------- 6. greedy collapse: O(1) window probe + serial fallback ----------------
__global__ void k_greedy() {
    __shared__ unsigned char s_mask[NN];
    __shared__ unsigned short s_tag[NN];
    __shared__ unsigned short s_own[NN];
    int b = blockIdx.x, lane = threadIdx.x;
    for (int i = lane; i < NN; i += 32) s_mask[i] = 1;
    __syncwarp();
    int nk = 0;
    const int W = EE / 32;
    unsigned cur = g_sedge[b][lane];
    for (int w = 0; w < W; w++) {
        unsigned nxt = (w + 1 < W) ? g_sedge[b][(w + 1) * 32 + lane] : 0u;
        int a = cur & 8191, b2 = (cur >> 13) & 8191, okv = (cur >> 26) & 1;
        int tent = okv && s_mask[a] && s_mask[b2];
        unsigned T = __ballot_sync(FULLM, tent);
        if (T) {
            if (tent) s_tag[a] = (unsigned short)w;
            __syncwarp();
            if (tent) s_own[b2] = (unsigned short)(w * 32 + lane);
            __syncwarp();
            int bad = 0;
            if (tent) {
                bad = (s_tag[b2] == (unsigned short)w) ||
                      (s_own[b2] != (unsigned short)(w * 32 + lane));
            }
            unsigned D = __ballot_sync(FULLM, bad);
            unsigned below = (1u << lane) - 1u;
            unsigned acc = 0;
            int cnt = __popc(T);
            if (!D) {
                if (nk + cnt <= TGT) { acc = T; nk += cnt; }
                else {
                    int rem = TGT - nk;
                    acc = __ballot_sync(FULLM, tent && (__popc(T & below) < rem));
                    nk = TGT;
                }
            } else {
                unsigned TT = T;
                while (TT) {
                    int t2 = __ffs(TT) - 1; TT &= TT - 1;
                    int at = __shfl_sync(FULLM, a, t2);
                    int bt = __shfl_sync(FULLM, b2, t2);
                    unsigned conf = __ballot_sync(FULLM, ((acc >> lane) & 1) && (b2 == at || b2 == bt));
                    if (!conf && nk < TGT) { acc |= 1u << t2; nk++; }
                }
            }
            if ((acc >> lane) & 1) { s_mask[b2] = 0; g_m[b][b2] = a; }
            __syncwarp();
            if (nk >= TGT) break;
        }
        cur = nxt;
    }
    for (int i = lane; i < NN; i += 32) g_mask[b][i] = s_mask[i];
}

// ---------------- 7. alive ranks + group CSR ----------------
__global__ void __launch_bounds__(1024) k_compact() {
    __shared__ unsigned s_tmp[33];
    __shared__ int s_cnt[KK];
    __shared__ int s_cur[KK];
    int b = blockIdx.x, tid = threadIdx.x;
    int base = tid * 8;
    unsigned mk[8]; unsigned c = 0;
#pragma unroll
    for (int i = 0; i < 8; i++) { mk[i] = (unsigned)g_mask[b][base + i]; c += mk[i]; }
    unsigned tot;
    unsigned ex = blockScanExcl1024(c, s_tmp, &tot);
    int run = (int)ex;
#pragma unroll
    for (int i = 0; i < 8; i++) { g_rank[b][base + i] = run; run += (int)mk[i]; }
    __syncthreads();
    for (int r = tid; r < KK; r += 1024) s_cnt[r] = 0;
    __syncthreads();
    for (int j = tid; j < NN; j += 1024) {
        int t = g_m[b][j];
        if (g_mask[b][t]) { int r = g_rank[b][t]; if (r < KK) atomicAdd(&s_cnt[r], 1); }
    }
    __syncthreads();
    int i4 = tid * 4; unsigned cv[4]; unsigned sum = 0;
#pragma unroll
    for (int i = 0; i < 4; i++) { cv[i] = (unsigned)s_cnt[i4 + i]; sum += cv[i]; }
    unsigned tot2;
    unsigned ex2 = blockScanExcl1024(sum, s_tmp, &tot2);
    int run2 = (int)ex2;
#pragma unroll
    for (int i = 0; i < 4; i++) { g_gstart[b][i4 + i] = run2; s_cur[i4 + i] = run2; run2 += (int)cv[i]; }
    if (tid == 1023) g_gstart[b][KK] = run2;
    __syncthreads();
    for (int j = tid; j < NN; j += 1024) {
        int t = g_m[b][j];
        if (g_mask[b][t]) {
            int r = g_rank[b][t];
            if (r < KK) { int pos = atomicAdd(&s_cur[r], 1); g_gsrc[b][pos] = (unsigned short)j; }
        }
    }
}

// ---------------- 8. pack A (f32 0/1) -> row-major bits via warp ballot ----------------
// warp handles 1024 consecutive floats -> 32 words. Coalesced LDG + VOTE: ~5 instr/word.
__global__ void __launch_bounds__(256) k_pack(const float* __restrict__ A) {
    int gw = (blockIdx.x * 256 + threadIdx.x) >> 5;   // global warp id (262144 total)
    int lane = threadIdx.x & 31;
    const float* base = A + (size_t)gw * 1024;
    unsigned myw = 0;
#pragma unroll
    for (int t = 0; t < 32; t++) {
        float v = base[t * 32 + lane];
        unsigned bal = __ballot_sync(FULLM, v != 0.0f);
        if (lane == t) myw = bal;
    }
    ((unsigned*)g_Ab)[(size_t)gw * 32 + lane] = myw;
}

// ---------------- 9. G1[r] = OR of A-bit rows in group(r)  (row merge) ----------------
__global__ void __launch_bounds__(1024) k_G1() {
    int b = blockIdx.y;
    int c = blockIdx.x * 4 + (threadIdx.x >> 8);
    int w = threadIdx.x & 255;
    int s = g_gstart[b][c], e = g_gstart[b][c + 1];
    unsigned v = 0;
    for (int i = s; i < e; i++) v |= g_Ab[b][g_gsrc[b][i]][w];
    g_G1[b][c][w] = v;
}

// ---------------- 10. bit transpose G1 (K x N) -> G1T (N x K) ----------------
__global__ void __launch_bounds__(1024) k_transT() {
    __shared__ __align__(16) unsigned wt[256 * 5];
    __shared__ __align__(16) unsigned outS[1024];
    int b = blockIdx.z, ct = blockIdx.y, jt = blockIdx.x;
    int tid = threadIdx.x;
    {
        int r = tid >> 2, w4 = tid & 3;
        wt[r * 5 + w4] = g_G1[b][ct * 256 + r][jt * 4 + w4];
    }
    __syncthreads();
    int w = tid >> 5, lane = tid & 31;
    int jw = w >> 3, iw = w & 7;
    unsigned s = wt[(iw * 32 + lane) * 5 + jw];
    unsigned myword = 0;
#pragma unroll 1
    for (int k = 0; k < 32; k++) {
        unsigned bt = __ballot_sync(FULLM, (s >> k) & 1);
        if (lane == k) myword = bt;
    }
    outS[(jw * 32 + lane) * 8 + iw] = myword;
    __syncthreads();
    int j = tid >> 3, ww = tid & 7;
    g_G1T[b][jt * 128 + j][ct * 8 + ww] = outS[tid];
}

// ---------------- 11. G2[c] = OR of G1T rows in group(c)  (col merge) ----------------
__global__ void __launch_bounds__(1024) k_G2() {
    int b = blockIdx.y;
    int r = blockIdx.x * 8 + (threadIdx.x >> 7);
    int w = threadIdx.x & 127;
    int s = g_gstart[b][r], e = g_gstart[b][r + 1];
    unsigned v = 0;
    for (int i = s; i < e; i++) v |= g_G1T[b][g_gsrc[b][i]][w];
    g_G2[b][r][w] = v;
}

// ---------------- 11b. final K x K bit transpose: G2 -> M2 ----------------
__global__ void __launch_bounds__(1024) k_transKK() {
    __shared__ __align__(16) unsigned wt[256 * 5];
    __shared__ __align__(16) unsigned outS[1024];
    int b = blockIdx.z, ct = blockIdx.y, jt = blockIdx.x;
    int tid = threadIdx.x;
    {
        int r = tid >> 2, w4 = tid & 3;
        wt[r * 5 + w4] = g_G2[b][ct * 256 + r][jt * 4 + w4];
    }
    __syncthreads();
    int w = tid >> 5, lane = tid & 31;
    int jw = w >> 3, iw = w & 7;
    unsigned s = wt[(iw * 32 + lane) * 5 + jw];
    unsigned myword = 0;
#pragma unroll 1
    for (int k = 0; k < 32; k++) {
        unsigned bt = __ballot_sync(FULLM, (s >> k) & 1);
        if (lane == k) myword = bt;
    }
    outS[(jw * 32 + lane) * 8 + iw] = myword;
    __syncthreads();
    int j = tid >> 3, ww = tid & 7;
    g_M2[b][jt * 128 + j][ct * 8 + ww] = outS[tid];
}

// ---------------- 12+13. expand bits -> float (diag cleared) + pooled features ----------
__global__ void k_expandfeat(const float* __restrict__ image, float* __restrict__ out) {
    int b = blockIdx.y;
    if (blockIdx.x < 16384) {
        int idx = blockIdx.x * 256 + threadIdx.x;     // 0 .. K*K/4-1
        int r = idx >> 10;
        int c4 = (idx & 1023) << 2;
        unsigned wv = g_M2[b][r][c4 >> 5];
        int sh = c4 & 31;
        float4 o;
        o.x = (((wv >> (sh + 0)) & 1) && (r != c4 + 0)) ? 1.f : 0.f;
        o.y = (((wv >> (sh + 1)) & 1) && (r != c4 + 1)) ? 1.f : 0.f;
        o.z = (((wv >> (sh + 2)) & 1) && (r != c4 + 2)) ? 1.f : 0.f;
        o.w = (((wv >> (sh + 3)) & 1) && (r != c4 + 3)) ? 1.f : 0.f;
        ((float4*)out)[((size_t)b * KK + r) * (KK / 4) + (idx & 1023)] = o;
    } else {
        int idx = (blockIdx.x - 16384) * 256 + threadIdx.x;  // 0 .. K*F-1
        int f = idx & (FF - 1);
        int r = idx >> 6;
        int s = g_gstart[b][r], e = g_gstart[b][r + 1];
        float acc = 0.f;
        for (int i = s; i < e; i++) {
            int j = g_gsrc[b][i];
            acc += image[((size_t)b * NN + j) * FF + f];
        }
        out[(size_t)BB * KK * KK + ((size_t)b * KK + r) * FF + f] = acc;
    }
}

// ---------------- launch ----------------
extern "C" void kernel_launch(void* const* d_in, const int* in_sizes, int n_in,
                              void* d_out, int out_size) {
    const float* adj = (const float*)d_in[0];       // bool promoted to f32 (0.0/1.0)
    const float* image = (const float*)d_in[1];
    const float* vs = (const float*)d_in[2];
    const int* edges = (const int*)d_in[3];
    float* out = (float*)d_out;

    static cudaStream_t s1 = nullptr;
    static cudaEvent_t evF = nullptr, evJ = nullptr;
    if (!s1) {
        cudaStreamCreateWithFlags(&s1, cudaStreamNonBlocking);
        cudaEventCreateWithFlags(&evF, cudaEventDisableTiming);
        cudaEventCreateWithFlags(&evJ, cudaEventDisableTiming);
    }

    // fork: pack (1GB adj read) overlaps the whole cost/sort/greedy chain
    cudaEventRecord(evF, 0);
    cudaStreamWaitEvent(s1, evF, 0);
    k_pack<<<32768, 256, 0, s1>>>(adj);

    k_vnorm<<<(BB * NN) / 256, 256>>>(image);
    k_keys<<<(BB * EE) / 256, 256>>>(edges, vs);
    for (int p = 0; p < 4; p++) {
        k_count<<<dim3(NBLK, BB), 256>>>(p);
        k_scan<<<BB, 1024>>>();
        k_scat<<<dim3(NBLK, BB), 256>>>(p, edges, p == 3);
    }
    k_greedy<<<BB, 32>>>();
    k_compact<<<BB, 1024>>>();

    // join pack before merges
    cudaEventRecord(evJ, s1);
    cudaStreamWaitEvent(0, evJ, 0);

    k_G1<<<dim3(KK / 4, BB), 1024>>>();
    k_transT<<<dim3(NN / 128, KK / 256, BB), 1024>>>();
    k_G2<<<dim3(KK / 8, BB), 1024>>>();
    k_transKK<<<dim3(KK / 128, KK / 256, BB), 1024>>>();
    k_expandfeat<<<dim3(16384 + (KK * FF) / 256, BB), 256>>>(image, out);
}